// round 1
// baseline (speedup 1.0000x reference)
#include <cuda_runtime.h>
#include <cuda_bf16.h>
#include <cstdint>

#define D 128
#define NWARPS 8
#define THREADS (NWARPS * 32)
#define SG 8              // scores per warp-group
#define LIST_MAX 4096     // max samples per relation (mean ~82 for B=16384, 200 rels)
#define HT_STRIDE 9       // padded stride for h-transpose staging (4-way STS conflict)

// dynamic smem layout (floats):
//  [0, D*D)                      : R matrix for this relation (64 KB)
//  [D*D, D*D+LIST_MAX)           : sample index list (as int)
//  [D*D+LIST_MAX, ... )          : per-warp hT staging, NWARPS * D * HT_STRIDE floats
#define SMEM_R_OFF    0
#define SMEM_LIST_OFF (D * D)
#define SMEM_HT_OFF   (D * D + LIST_MAX)
#define SMEM_FLOATS   (SMEM_HT_OFF + NWARPS * D * HT_STRIDE)
#define SMEM_BYTES    (SMEM_FLOATS * 4)

__global__ __launch_bounds__(THREADS) void rescal_kernel(
    const int* __restrict__ heads,
    const int* __restrict__ tails,
    const int* __restrict__ nheads,
    const int* __restrict__ ntails,
    const int* __restrict__ rels,
    const float* __restrict__ ent,
    const float* __restrict__ relm,
    float* __restrict__ out,
    int B)
{
    extern __shared__ float smem[];
    float* Rs = smem + SMEM_R_OFF;
    int* list = (int*)(smem + SMEM_LIST_OFF);
    __shared__ int cnt;

    const int r   = blockIdx.x;
    const int tid = threadIdx.x;
    const int wid = tid >> 5;
    const int lane = tid & 31;

    if (tid == 0) cnt = 0;

    // ---- stage R into smem (coalesced float4) ----
    {
        const float4* Rg = (const float4*)(relm + (size_t)r * D * D);
        float4* Rs4 = (float4*)Rs;
        #pragma unroll
        for (int i = tid; i < D * D / 4; i += THREADS)
            Rs4[i] = Rg[i];
    }
    __syncthreads();

    // ---- scan relations, collect matching samples ----
    for (int b = tid; b < B; b += THREADS) {
        if (rels[b] == r) {
            int p = atomicAdd(&cnt, 1);
            if (p < LIST_MAX) list[p] = b;
        }
    }
    __syncthreads();

    const int n = min(cnt, LIST_MAX);
    const int nscore = 2 * n;                      // even = pos, odd = neg
    const int ngroups = (nscore + SG - 1) / SG;

    float* myhT = smem + SMEM_HT_OFF + wid * (D * HT_STRIDE);

    for (int g = wid; g < ngroups; g += NWARPS) {
        const int s0 = g * SG;

        // ---- gather: h -> smem transpose, t -> registers ----
        float4 treg[SG];
        int outidx[SG];
        #pragma unroll
        for (int s = 0; s < SG; s++) {
            const int si = s0 + s;
            float4 hv = make_float4(0.f, 0.f, 0.f, 0.f);
            float4 tv = make_float4(0.f, 0.f, 0.f, 0.f);
            int oi = -1;
            if (si < nscore) {
                const int b = list[si >> 1];
                const bool neg = (si & 1);
                const int hi = neg ? nheads[b] : heads[b];
                const int ti = neg ? ntails[b] : tails[b];
                hv = ((const float4*)(ent + (size_t)hi * D))[lane];
                tv = ((const float4*)(ent + (size_t)ti * D))[lane];
                oi = neg ? (B + b) : b;
            }
            treg[s] = tv;
            outidx[s] = oi;
            const int d0 = lane * 4;
            myhT[(d0 + 0) * HT_STRIDE + s] = hv.x;
            myhT[(d0 + 1) * HT_STRIDE + s] = hv.y;
            myhT[(d0 + 2) * HT_STRIDE + s] = hv.z;
            myhT[(d0 + 3) * HT_STRIDE + s] = hv.w;
        }
        __syncwarp();

        // ---- y_e^{(s)} = sum_d h_d^{(s)} * R[d][e], e = 4*lane + j ----
        float y[SG][4];
        #pragma unroll
        for (int s = 0; s < SG; s++) {
            y[s][0] = 0.f; y[s][1] = 0.f; y[s][2] = 0.f; y[s][3] = 0.f;
        }

        const float4* Rs4row = (const float4*)Rs;
        #pragma unroll 4
        for (int d = 0; d < D; d++) {
            const float4 rr = Rs4row[d * (D / 4) + lane];
            const float* hrow = myhT + d * HT_STRIDE;
            #pragma unroll
            for (int s = 0; s < SG; s++) {
                const float hd = hrow[s];
                y[s][0] = fmaf(hd, rr.x, y[s][0]);
                y[s][1] = fmaf(hd, rr.y, y[s][1]);
                y[s][2] = fmaf(hd, rr.z, y[s][2]);
                y[s][3] = fmaf(hd, rr.w, y[s][3]);
            }
        }

        // ---- score = sum_e y_e * t_e ; warp reduce ; store ----
        #pragma unroll
        for (int s = 0; s < SG; s++) {
            float p = y[s][0] * treg[s].x + y[s][1] * treg[s].y
                    + y[s][2] * treg[s].z + y[s][3] * treg[s].w;
            #pragma unroll
            for (int o = 16; o; o >>= 1)
                p += __shfl_xor_sync(0xFFFFFFFFu, p, o);
            if (lane == 0 && outidx[s] >= 0)
                out[outidx[s]] = p;
        }
        __syncwarp();   // staging buffer reuse
    }
}

extern "C" void kernel_launch(void* const* d_in, const int* in_sizes, int n_in,
                              void* d_out, int out_size) {
    const int* heads  = (const int*)d_in[0];
    const int* tails  = (const int*)d_in[1];
    const int* nheads = (const int*)d_in[2];
    const int* ntails = (const int*)d_in[3];
    const int* rels   = (const int*)d_in[4];
    const float* ent  = (const float*)d_in[5];
    const float* relm = (const float*)d_in[6];
    float* out = (float*)d_out;

    const int B = in_sizes[0];
    const int n_rel = in_sizes[6] / (D * D);

    cudaFuncSetAttribute(rescal_kernel,
                         cudaFuncAttributeMaxDynamicSharedMemorySize, SMEM_BYTES);

    rescal_kernel<<<n_rel, THREADS, SMEM_BYTES>>>(
        heads, tails, nheads, ntails, rels, ent, relm, out, B);
}

// round 2
// speedup vs baseline: 1.1642x; 1.1642x over previous
#include <cuda_runtime.h>
#include <cuda_bf16.h>
#include <cstdint>

#define D 128
#define SLICES 4
#define DSLICE (D / SLICES)        // 32 rows of R per CTA
#define NWARPS 8
#define THREADS (NWARPS * 32)
#define SG 8                       // scores per warp-group
#define HT_STRIDE 10               // even (8B-aligned pairs) + conflict-free stores
#define LIST_MAX 2048
#define NREL_MAX 256
#define B_MAX 16384

// global scratch (allocation-free rule: __device__ arrays)
__device__ int   g_cnt[NREL_MAX];
__device__ int   g_list[NREL_MAX * LIST_MAX];
__device__ float g_part[SLICES][2 * B_MAX];

// smem: R slice (DSLICE*D floats = 16KB) + per-warp hT staging
#define SMEM_R_FLOATS (DSLICE * D)
#define SMEM_HT_FLOATS (NWARPS * DSLICE * HT_STRIDE)
#define SMEM_BYTES ((SMEM_R_FLOATS + SMEM_HT_FLOATS) * 4)

#define PACK_F32X2(out, lo, hi) \
    asm("mov.b64 %0, {%1, %2};" : "=l"(out) : "f"(lo), "f"(hi))
#define UNPACK_F32X2(lo, hi, in) \
    asm("mov.b64 {%0, %1}, %2;" : "=f"(lo), "=f"(hi) : "l"(in))
#define FMA_F32X2(d, a, b, c) \
    asm("fma.rn.f32x2 %0, %1, %2, %3;" : "=l"(d) : "l"(a), "l"(b), "l"(c))

__global__ void zero_cnt_kernel() {
    if (threadIdx.x < NREL_MAX) g_cnt[threadIdx.x] = 0;
}

__global__ void bin_kernel(const int* __restrict__ rels, int B) {
    int b = blockIdx.x * blockDim.x + threadIdx.x;
    if (b < B) {
        int r = rels[b];
        int p = atomicAdd(&g_cnt[r], 1);
        if (p < LIST_MAX) g_list[r * LIST_MAX + p] = b;
    }
}

__global__ __launch_bounds__(THREADS, 2) void rescal_main_kernel(
    const int* __restrict__ heads,
    const int* __restrict__ tails,
    const int* __restrict__ nheads,
    const int* __restrict__ ntails,
    const float* __restrict__ ent,
    const float* __restrict__ relm,
    int B)
{
    extern __shared__ float smem[];
    float* Rs = smem;                      // [DSLICE][D]
    const int r     = blockIdx.x >> 2;
    const int slice = blockIdx.x & 3;
    const int d_base = slice * DSLICE;
    const int tid  = threadIdx.x;
    const int wid  = tid >> 5;
    const int lane = tid & 31;

    // ---- stage R slice (rows d_base..d_base+31) ----
    {
        const float4* Rg = (const float4*)(relm + (size_t)r * D * D + (size_t)d_base * D);
        float4* Rs4 = (float4*)Rs;
        #pragma unroll
        for (int i = tid; i < SMEM_R_FLOATS / 4; i += THREADS)
            Rs4[i] = Rg[i];
    }
    __syncthreads();

    const int n = min(g_cnt[r], LIST_MAX);
    const int nscore = 2 * n;
    const int ngroups = (nscore + SG - 1) / SG;
    const int* mylist = g_list + r * LIST_MAX;

    float* myhT = smem + SMEM_R_FLOATS + wid * (DSLICE * HT_STRIDE);
    const float4* Rs4 = (const float4*)Rs;

    for (int g = wid; g < ngroups; g += NWARPS) {
        const int s0 = g * SG;

        // ---- gather h slices into transposed smem staging ----
        // pass p: lane -> (s_sub = lane>>3, i = lane&7), score s = 4p + s_sub
        #pragma unroll
        for (int p = 0; p < 2; p++) {
            const int s_sub = lane >> 3;
            const int i = lane & 7;
            const int s = 4 * p + s_sub;
            const int si = s0 + s;
            float4 hv = make_float4(0.f, 0.f, 0.f, 0.f);
            if (si < nscore) {
                const int b = mylist[si >> 1];
                const int hi = (si & 1) ? nheads[b] : heads[b];
                hv = ((const float4*)(ent + (size_t)hi * D + d_base))[i];
            }
            const int row0 = 4 * i;
            myhT[(row0 + 0) * HT_STRIDE + s] = hv.x;
            myhT[(row0 + 1) * HT_STRIDE + s] = hv.y;
            myhT[(row0 + 2) * HT_STRIDE + s] = hv.z;
            myhT[(row0 + 3) * HT_STRIDE + s] = hv.w;
        }
        __syncwarp();

        // ---- packed-f32x2 accumulation: y[sp][e] over d-slice ----
        // sp packs scores (2sp, 2sp+1) in (lo, hi) lanes
        unsigned long long y[4][4];
        #pragma unroll
        for (int sp = 0; sp < 4; sp++)
            #pragma unroll
            for (int c = 0; c < 4; c++)
                y[sp][c] = 0ULL;

        #pragma unroll 4
        for (int d = 0; d < DSLICE; d++) {
            const float4 rr = Rs4[d * (D / 4) + lane];
            unsigned long long rx, ry, rz, rw;
            PACK_F32X2(rx, rr.x, rr.x);
            PACK_F32X2(ry, rr.y, rr.y);
            PACK_F32X2(rz, rr.z, rr.z);
            PACK_F32X2(rw, rr.w, rr.w);
            const unsigned long long* hp =
                (const unsigned long long*)(myhT + d * HT_STRIDE);
            #pragma unroll
            for (int sp = 0; sp < 4; sp++) {
                const unsigned long long h2 = hp[sp];
                FMA_F32X2(y[sp][0], h2, rx, y[sp][0]);
                FMA_F32X2(y[sp][1], h2, ry, y[sp][1]);
                FMA_F32X2(y[sp][2], h2, rz, y[sp][2]);
                FMA_F32X2(y[sp][3], h2, rw, y[sp][3]);
            }
        }

        // ---- epilogue: dot with t, warp-reduce, write partial ----
        #pragma unroll
        for (int s = 0; s < SG; s++) {
            const int si = s0 + s;
            if (si < nscore) {
                const int b = mylist[si >> 1];
                const bool neg = (si & 1);
                const int ti = neg ? ntails[b] : tails[b];
                const float4 tv = ((const float4*)(ent + (size_t)ti * D))[lane];
                const int sp = s >> 1;
                float v0, v1, w0, w1, x0, x1, z0, z1;
                UNPACK_F32X2(v0, v1, y[sp][0]);
                UNPACK_F32X2(w0, w1, y[sp][1]);
                UNPACK_F32X2(x0, x1, y[sp][2]);
                UNPACK_F32X2(z0, z1, y[sp][3]);
                float p = (s & 1)
                    ? (v1 * tv.x + w1 * tv.y + x1 * tv.z + z1 * tv.w)
                    : (v0 * tv.x + w0 * tv.y + x0 * tv.z + z0 * tv.w);
                #pragma unroll
                for (int o = 16; o; o >>= 1)
                    p += __shfl_xor_sync(0xFFFFFFFFu, p, o);
                if (lane == 0) {
                    const int oi = neg ? (B + b) : b;
                    g_part[slice][oi] = p;
                }
            }
        }
        __syncwarp();   // staging buffer reuse
    }
}

__global__ void reduce_kernel(float* __restrict__ out, int n2) {
    int i = blockIdx.x * blockDim.x + threadIdx.x;
    if (i < n2) {
        out[i] = ((g_part[0][i] + g_part[1][i]) +
                  (g_part[2][i] + g_part[3][i]));
    }
}

extern "C" void kernel_launch(void* const* d_in, const int* in_sizes, int n_in,
                              void* d_out, int out_size) {
    const int* heads  = (const int*)d_in[0];
    const int* tails  = (const int*)d_in[1];
    const int* nheads = (const int*)d_in[2];
    const int* ntails = (const int*)d_in[3];
    const int* rels   = (const int*)d_in[4];
    const float* ent  = (const float*)d_in[5];
    const float* relm = (const float*)d_in[6];
    float* out = (float*)d_out;

    const int B = in_sizes[0];
    const int n_rel = in_sizes[6] / (D * D);

    zero_cnt_kernel<<<1, 256>>>();
    bin_kernel<<<(B + 255) / 256, 256>>>(rels, B);

    cudaFuncSetAttribute(rescal_main_kernel,
                         cudaFuncAttributeMaxDynamicSharedMemorySize, SMEM_BYTES);
    rescal_main_kernel<<<n_rel * SLICES, THREADS, SMEM_BYTES>>>(
        heads, tails, nheads, ntails, ent, relm, B);

    reduce_kernel<<<(2 * B + 255) / 256, 256>>>(out, 2 * B);
}

// round 4
// speedup vs baseline: 1.5613x; 1.3410x over previous
#include <cuda_runtime.h>
#include <cuda_bf16.h>
#include <cstdint>

#define D 128
#define SLICES 4
#define DSLICE (D / SLICES)        // 32 rows of R per CTA
#define NWARPS 8
#define THREADS (NWARPS * 32)
#define SG 8                       // scores per warp-group
#define HT_STRIDE 10               // even (8B-aligned pairs), conflict-light stores
#define LIST_MAX 2048
#define NREL_MAX 256
#define B_MAX 16384

// global scratch (allocation-free rule: __device__ arrays)
__device__ int   g_cnt[NREL_MAX];            // zero at load; re-zeroed by reduce_kernel
__device__ int   g_list[NREL_MAX * LIST_MAX];
__device__ float g_part[SLICES][2 * B_MAX];

#define SMEM_R_FLOATS (DSLICE * D)
#define SMEM_HT_FLOATS (NWARPS * DSLICE * HT_STRIDE)
#define SMEM_BYTES ((SMEM_R_FLOATS + SMEM_HT_FLOATS) * 4)

#define PACK_F32X2(out, lo, hi) \
    asm("mov.b64 %0, {%1, %2};" : "=l"(out) : "f"(lo), "f"(hi))
#define UNPACK_F32X2(lo, hi, in) \
    asm("mov.b64 {%0, %1}, %2;" : "=f"(lo), "=f"(hi) : "l"(in))
#define FMA_F32X2(d, a, b, c) \
    asm("fma.rn.f32x2 %0, %1, %2, %3;" : "=l"(d) : "l"(a), "l"(b), "l"(c))
#define ADD_F32X2(d, a, b) \
    asm("add.rn.f32x2 %0, %1, %2;" : "=l"(d) : "l"(a), "l"(b))

// packed warp reduction: sums lo and hi lanes independently across the warp
__device__ __forceinline__ unsigned long long warp_sum_x2(unsigned long long v) {
    #pragma unroll
    for (int o = 16; o; o >>= 1) {
        unsigned lo = (unsigned)v, hi = (unsigned)(v >> 32);
        unsigned slo = __shfl_xor_sync(0xFFFFFFFFu, lo, o);
        unsigned shi = __shfl_xor_sync(0xFFFFFFFFu, hi, o);
        unsigned long long sv = ((unsigned long long)shi << 32) | slo;
        ADD_F32X2(v, v, sv);
    }
    return v;
}

__global__ void bin_kernel(const int* __restrict__ rels, int B) {
    int b = blockIdx.x * blockDim.x + threadIdx.x;
    if (b < B) {
        int r = rels[b];
        int p = atomicAdd(&g_cnt[r], 1);
        if (p < LIST_MAX) g_list[r * LIST_MAX + p] = b;
    }
}

__global__ __launch_bounds__(THREADS, 2) void rescal_main_kernel(
    const int* __restrict__ heads,
    const int* __restrict__ tails,
    const int* __restrict__ nheads,
    const int* __restrict__ ntails,
    const float* __restrict__ ent,
    const float* __restrict__ relm,
    int B)
{
    extern __shared__ float smem[];
    float* Rs = smem;                      // [DSLICE][D]
    const int r      = blockIdx.x >> 2;
    const int slice  = blockIdx.x & 3;
    const int d_base = slice * DSLICE;
    const int tid  = threadIdx.x;
    const int wid  = tid >> 5;
    const int lane = tid & 31;

    // ---- stage R slice ----
    {
        const float4* Rg = (const float4*)(relm + (size_t)r * D * D + (size_t)d_base * D);
        float4* Rs4w = (float4*)Rs;
        #pragma unroll
        for (int i = tid; i < SMEM_R_FLOATS / 4; i += THREADS)
            Rs4w[i] = Rg[i];
    }
    __syncthreads();

    const int n = min(g_cnt[r], LIST_MAX);
    const int nscore = 2 * n;
    const int ngroups = (nscore + SG - 1) / SG;
    const int* mylist = g_list + r * LIST_MAX;

    float* myhT = smem + SMEM_R_FLOATS + wid * (DSLICE * HT_STRIDE);
    const float4* Rs4 = (const float4*)Rs;

    const int s_sub = lane >> 3;    // 0..3
    const int ivec  = lane & 7;     // 0..7

    // ---- prefetch h for first group ----
    float4 hA[2];
    {
        const int g0 = wid;
        #pragma unroll
        for (int p = 0; p < 2; p++) {
            const int si = g0 * SG + 4 * p + s_sub;
            float4 hv = make_float4(0.f, 0.f, 0.f, 0.f);
            if (g0 < ngroups && si < nscore) {
                const int b = mylist[si >> 1];
                const int hi = (si & 1) ? nheads[b] : heads[b];
                hv = ((const float4*)(ent + (size_t)hi * D + d_base))[ivec];
            }
            hA[p] = hv;
        }
    }

    for (int g = wid; g < ngroups; g += NWARPS) {
        const int s0 = g * SG;

        // ---- stage prefetched h (transposed) ----
        __syncwarp();
        #pragma unroll
        for (int p = 0; p < 2; p++) {
            const int s = 4 * p + s_sub;
            const int row0 = 4 * ivec;
            myhT[(row0 + 0) * HT_STRIDE + s] = hA[p].x;
            myhT[(row0 + 1) * HT_STRIDE + s] = hA[p].y;
            myhT[(row0 + 2) * HT_STRIDE + s] = hA[p].z;
            myhT[(row0 + 3) * HT_STRIDE + s] = hA[p].w;
        }
        __syncwarp();

        // ---- issue t loads for THIS group (latency hidden under d-loop) ----
        float4 tv[SG];
        int oi[SG];
        #pragma unroll
        for (int s = 0; s < SG; s++) {
            const int si = s0 + s;
            float4 t4 = make_float4(0.f, 0.f, 0.f, 0.f);
            int o = -1;
            if (si < nscore) {
                const int b = mylist[si >> 1];
                const bool neg = (si & 1);
                const int ti = neg ? ntails[b] : tails[b];
                t4 = ((const float4*)(ent + (size_t)ti * D))[lane];
                o = neg ? (B + b) : b;
            }
            tv[s] = t4;
            oi[s] = o;
        }

        // ---- prefetch h for NEXT group ----
        {
            const int gn = g + NWARPS;
            #pragma unroll
            for (int p = 0; p < 2; p++) {
                const int si = gn * SG + 4 * p + s_sub;
                float4 hv = make_float4(0.f, 0.f, 0.f, 0.f);
                if (gn < ngroups && si < nscore) {
                    const int b = mylist[si >> 1];
                    const int hi = (si & 1) ? nheads[b] : heads[b];
                    hv = ((const float4*)(ent + (size_t)hi * D + d_base))[ivec];
                }
                hA[p] = hv;
            }
        }

        // ---- packed-f32x2 accumulation ----
        unsigned long long y[4][4];
        #pragma unroll
        for (int sp = 0; sp < 4; sp++)
            #pragma unroll
            for (int c = 0; c < 4; c++)
                y[sp][c] = 0ULL;

        #pragma unroll 4
        for (int d = 0; d < DSLICE; d++) {
            const float4 rr = Rs4[d * (D / 4) + lane];
            unsigned long long rx, ry, rz, rw;
            PACK_F32X2(rx, rr.x, rr.x);
            PACK_F32X2(ry, rr.y, rr.y);
            PACK_F32X2(rz, rr.z, rr.z);
            PACK_F32X2(rw, rr.w, rr.w);
            const unsigned long long* hp =
                (const unsigned long long*)(myhT + d * HT_STRIDE);
            #pragma unroll
            for (int sp = 0; sp < 4; sp++) {
                const unsigned long long h2 = hp[sp];
                FMA_F32X2(y[sp][0], h2, rx, y[sp][0]);
                FMA_F32X2(y[sp][1], h2, ry, y[sp][1]);
                FMA_F32X2(y[sp][2], h2, rz, y[sp][2]);
                FMA_F32X2(y[sp][3], h2, rw, y[sp][3]);
            }
        }

        // ---- epilogue: packed dot with t, packed warp reduce, write ----
        #pragma unroll
        for (int sp = 0; sp < 4; sp++) {
            const int siA = s0 + 2 * sp;
            if (siA < nscore) {             // uniform across warp
                const float4 tA = tv[2 * sp];
                const float4 tB = tv[2 * sp + 1];
                unsigned long long tx, ty, tz, tw;
                PACK_F32X2(tx, tA.x, tB.x);
                PACK_F32X2(ty, tA.y, tB.y);
                PACK_F32X2(tz, tA.z, tB.z);
                PACK_F32X2(tw, tA.w, tB.w);
                unsigned long long acc = 0ULL, acc2 = 0ULL;
                FMA_F32X2(acc,  y[sp][0], tx, acc);
                FMA_F32X2(acc2, y[sp][1], ty, acc2);
                FMA_F32X2(acc,  y[sp][2], tz, acc);
                FMA_F32X2(acc2, y[sp][3], tw, acc2);
                ADD_F32X2(acc, acc, acc2);
                acc = warp_sum_x2(acc);
                if (lane == 0) {
                    float pA, pB;
                    UNPACK_F32X2(pA, pB, acc);
                    g_part[slice][oi[2 * sp]] = pA;
                    if (oi[2 * sp + 1] >= 0)
                        g_part[slice][oi[2 * sp + 1]] = pB;
                }
            }
        }
    }
}

__global__ void reduce_kernel(float* __restrict__ out, int n4) {
    int i = blockIdx.x * blockDim.x + threadIdx.x;
    if (i < n4) {
        const float4 a = ((const float4*)g_part[0])[i];
        const float4 b = ((const float4*)g_part[1])[i];
        const float4 c = ((const float4*)g_part[2])[i];
        const float4 d = ((const float4*)g_part[3])[i];
        float4 o;
        o.x = (a.x + b.x) + (c.x + d.x);
        o.y = (a.y + b.y) + (c.y + d.y);
        o.z = (a.z + b.z) + (c.z + d.z);
        o.w = (a.w + b.w) + (c.w + d.w);
        ((float4*)out)[i] = o;
    }
    // reset relation counters for the next graph replay
    if (blockIdx.x == 0 && threadIdx.x < NREL_MAX) g_cnt[threadIdx.x] = 0;
}

extern "C" void kernel_launch(void* const* d_in, const int* in_sizes, int n_in,
                              void* d_out, int out_size) {
    const int* heads  = (const int*)d_in[0];
    const int* tails  = (const int*)d_in[1];
    const int* nheads = (const int*)d_in[2];
    const int* ntails = (const int*)d_in[3];
    const int* rels   = (const int*)d_in[4];
    const float* ent  = (const float*)d_in[5];
    const float* relm = (const float*)d_in[6];
    float* out = (float*)d_out;

    const int B = in_sizes[0];
    const int n_rel = in_sizes[6] / (D * D);

    bin_kernel<<<(B + 255) / 256, 256>>>(rels, B);

    rescal_main_kernel<<<n_rel * SLICES, THREADS, SMEM_BYTES>>>(
        heads, tails, nheads, ntails, ent, relm, B);

    const int n4 = (2 * B) / 4;
    reduce_kernel<<<(n4 + 255) / 256, 256>>>(out, n4);
}